// round 4
// baseline (speedup 1.0000x reference)
#include <cuda_runtime.h>
#include <math.h>

// Problem dims
#define BB 2048
#define TT 128
#define VV 25
#define HH 512
#define G4 2048   // 4*H
#define NC 100

// Tiling
#define BM 128
#define BJ 32          // j-columns per CTA; effective N tile = BJ*4 = 128 gate cols
#define BK 16
#define LDS_STRIDE 132 // 128 + 4 pad

// Persistent state (device globals: no allocation allowed)
__device__ float g_h[2][(size_t)BB * HH];   // ping-pong hidden state
__device__ float g_c[(size_t)BB * HH];      // cell state (in-place, CTA-private cells)

__device__ __forceinline__ unsigned long long ffma2(unsigned long long a,
                                                    unsigned long long b,
                                                    unsigned long long c) {
    unsigned long long d;
    asm("fma.rn.f32x2 %0, %1, %2, %3;" : "=l"(d) : "l"(a), "l"(b), "l"(c));
    return d;
}
__device__ __forceinline__ unsigned long long pack2(float x) {
    unsigned long long d;
    asm("mov.b64 %0, {%1, %1};" : "=l"(d) : "f"(x));
    return d;
}
__device__ __forceinline__ float2 unpack2(unsigned long long v) {
    float2 r;
    asm("mov.b64 {%0, %1}, %2;" : "=f"(r.x), "=f"(r.y) : "l"(v));
    return r;
}
__device__ __forceinline__ float sigmoidf_(float x) {
    return 1.0f / (1.0f + __expf(-x));
}

__global__ void init_state_kernel() {
    size_t i = (size_t)blockIdx.x * blockDim.x + threadIdx.x;
    size_t n = (size_t)BB * HH;
    if (i < n) {
        g_h[0][i] = 0.0f;
        g_c[i]    = 0.0f;
    }
}

// One LSTM timestep:
//   gates[b, g*H+j] = x[b,t,:]@W_ih[g*H+j,:] + h[b,:]@W_hh[g*H+j,:] + b_ih + b_hh
//   c = sig(f)*c + sig(i)*tanh(g);  h = sig(o)*tanh(c)
// CTA tile: BM rows x BJ hidden units (x 4 gates) = 128x128 accumulator tile.
// Column layout within tile: col = jl*4 + gate  (so all 4 gates of a unit sit in one thread).
__global__ __launch_bounds__(256, 2) void lstm_step_kernel(
    const float* __restrict__ msgs,
    const float* __restrict__ W_ih,
    const float* __restrict__ W_hh,
    const float* __restrict__ b_ih,
    const float* __restrict__ b_hh,
    int t)
{
    __shared__ __align__(16) float As[BK][LDS_STRIDE];
    __shared__ __align__(16) float Bs[BK][LDS_STRIDE];

    const float* h_in  = g_h[t & 1];
    float*       h_out = g_h[(t + 1) & 1];

    const int tid = threadIdx.x;
    const int tx  = tid & 15;   // 0..15 -> 2 hidden units each
    const int ty  = tid >> 4;   // 0..15 -> 8 rows each
    const int row0 = blockIdx.x * BM;
    const int j0   = blockIdx.y * BJ;

    unsigned long long acc2[8][4];
    #pragma unroll
    for (int i = 0; i < 8; i++)
        #pragma unroll
        for (int j = 0; j < 4; j++) acc2[i][j] = 0ULL;

    // Unified K: [0,512) from h_in/W_hh, [512,537) from msgs/W_ih, zero-pad to 544.
    for (int kc = 0; kc < 544; kc += BK) {
        // --- load A tile (activations): 128 rows x 16 k ---
        #pragma unroll
        for (int l = 0; l < 2; l++) {
            int p  = tid + l * 256;   // 0..511 float4 slots
            int r  = p >> 2;          // 0..127
            int kq = p & 3;           // 0..3
            int k  = kc + kq * 4;
            float4 v;
            if (k < HH) {
                v = *(const float4*)&h_in[(size_t)(row0 + r) * HH + k];
            } else {
                int kv = k - HH;
                const float* xp = &msgs[((size_t)(row0 + r) * TT + t) * VV];
                v.x = (kv + 0 < VV) ? xp[kv + 0] : 0.0f;
                v.y = (kv + 1 < VV) ? xp[kv + 1] : 0.0f;
                v.z = (kv + 2 < VV) ? xp[kv + 2] : 0.0f;
                v.w = (kv + 3 < VV) ? xp[kv + 3] : 0.0f;
            }
            As[kq * 4 + 0][r] = v.x;
            As[kq * 4 + 1][r] = v.y;
            As[kq * 4 + 2][r] = v.z;
            As[kq * 4 + 3][r] = v.w;
        }
        // --- load B tile (weights): 128 gate-cols x 16 k ---
        #pragma unroll
        for (int l = 0; l < 2; l++) {
            int p  = tid + l * 256;
            int c  = p >> 2;          // 0..127 tile column
            int kq = p & 3;
            int k  = kc + kq * 4;
            int jl = c >> 2;
            int g  = c & 3;
            int wrow = g * HH + j0 + jl;
            float4 v;
            if (k < HH) {
                v = *(const float4*)&W_hh[(size_t)wrow * HH + k];
            } else {
                int kv = k - HH;
                const float* wp = &W_ih[(size_t)wrow * VV];
                v.x = (kv + 0 < VV) ? wp[kv + 0] : 0.0f;
                v.y = (kv + 1 < VV) ? wp[kv + 1] : 0.0f;
                v.z = (kv + 2 < VV) ? wp[kv + 2] : 0.0f;
                v.w = (kv + 3 < VV) ? wp[kv + 3] : 0.0f;
            }
            Bs[kq * 4 + 0][c] = v.x;
            Bs[kq * 4 + 1][c] = v.y;
            Bs[kq * 4 + 2][c] = v.z;
            Bs[kq * 4 + 3][c] = v.w;
        }
        __syncthreads();

        #pragma unroll
        for (int k = 0; k < BK; k++) {
            float a[8];
            *(float4*)&a[0] = *(const float4*)&As[k][ty * 8];
            *(float4*)&a[4] = *(const float4*)&As[k][ty * 8 + 4];
            ulonglong2 t0 = *(const ulonglong2*)&Bs[k][tx * 8];
            ulonglong2 t1 = *(const ulonglong2*)&Bs[k][tx * 8 + 4];
            unsigned long long b2[4] = {t0.x, t0.y, t1.x, t1.y};
            #pragma unroll
            for (int i = 0; i < 8; i++) {
                unsigned long long a2 = pack2(a[i]);
                #pragma unroll
                for (int j = 0; j < 4; j++)
                    acc2[i][j] = ffma2(a2, b2[j], acc2[i][j]);
            }
        }
        __syncthreads();
    }

    // --- fused LSTM elementwise epilogue ---
    float bia[2][4];
    #pragma unroll
    for (int jj = 0; jj < 2; jj++) {
        int j = j0 + tx * 2 + jj;
        #pragma unroll
        for (int g = 0; g < 4; g++)
            bia[jj][g] = b_ih[g * HH + j] + b_hh[g * HH + j];
    }

    #pragma unroll
    for (int i = 0; i < 8; i++) {
        int row = row0 + ty * 8 + i;
        #pragma unroll
        for (int jj = 0; jj < 2; jj++) {
            float2 p01 = unpack2(acc2[i][jj * 2 + 0]);  // gates i, f
            float2 p23 = unpack2(acc2[i][jj * 2 + 1]);  // gates g, o
            float gi = sigmoidf_(p01.x + bia[jj][0]);
            float gf = sigmoidf_(p01.y + bia[jj][1]);
            float gg = tanhf(p23.x + bia[jj][2]);
            float go = sigmoidf_(p23.y + bia[jj][3]);
            size_t idx = (size_t)row * HH + (j0 + tx * 2 + jj);
            float cn = gf * g_c[idx] + gi * gg;
            g_c[idx] = cn;
            h_out[idx] = go * tanhf(cn);
        }
    }
}

// out[b, cls] = h_last[b,:] @ W_fc[cls,:] + b_fc[cls];  h_last lives in g_h[0] (T even)
__global__ void fc_kernel(const float* __restrict__ W_fc,
                          const float* __restrict__ b_fc,
                          float* __restrict__ out)
{
    __shared__ float hs[HH];
    int b = blockIdx.x;
    const float* hrow = g_h[0] + (size_t)b * HH;
    for (int k = threadIdx.x; k < HH; k += blockDim.x) hs[k] = hrow[k];
    __syncthreads();
    int cls = threadIdx.x;
    if (cls < NC) {
        const float* w = &W_fc[(size_t)cls * HH];
        float acc = 0.0f;
        #pragma unroll 8
        for (int k = 0; k < HH; k++) acc += hs[k] * w[k];
        out[(size_t)b * NC + cls] = acc + b_fc[cls];
    }
}

extern "C" void kernel_launch(void* const* d_in, const int* in_sizes, int n_in,
                              void* d_out, int out_size)
{
    const float* msgs = (const float*)d_in[0];
    const float* W_ih = (const float*)d_in[1];
    const float* W_hh = (const float*)d_in[2];
    const float* b_ih = (const float*)d_in[3];
    const float* b_hh = (const float*)d_in[4];
    const float* W_fc = (const float*)d_in[5];
    const float* b_fc = (const float*)d_in[6];
    float* out = (float*)d_out;

    init_state_kernel<<<(BB * HH + 255) / 256, 256>>>();

    dim3 grid(BB / BM, HH / BJ);  // 16 x 16
    for (int t = 0; t < TT; t++) {
        lstm_step_kernel<<<grid, 256>>>(msgs, W_ih, W_hh, b_ih, b_hh, t);
    }

    fc_kernel<<<BB, 128>>>(W_fc, b_fc, out);
}

// round 7
// speedup vs baseline: 2.0979x; 2.0979x over previous
#include <cuda_runtime.h>
#include <cuda_fp16.h>
#include <math.h>
#include <stdint.h>

// ---- dims ----
#define BB 2048
#define TT 128
#define VV 25
#define HH 512
#define NC 100
#define KTOT 544          // 512 (h) + 32 (x padded from 25)
#define TM 128
#define TN 128
#define KCH 32            // K per chunk
#define NCH 17            // 544/32

// smem: rows of 32 halves padded to 80B (conflict-free ldmatrix)
#define ROWB 80
#define TILE_BYTES (128 * ROWB)         // 10240
#define STAGE_BYTES (4 * TILE_BYTES)    // Ahi, Alo, Bhi, Blo = 40960
#define SMEM_TOTAL (2 * STAGE_BYTES)    // 81920

// ---- persistent device state ----
__device__ __align__(1024) __half g_W_hi[2048][KTOT];   // permuted: row C=4j+gate, cols k
__device__ __align__(1024) __half g_W_lo[2048][KTOT];
__device__ __align__(1024) __half g_x_hi[TT][BB][32];
__device__ __align__(1024) __half g_x_lo[TT][BB][32];
__device__ __align__(1024) __half g_h_hi[2][BB][HH];
__device__ __align__(1024) __half g_h_lo[2][BB][HH];
__device__ __align__(1024) float  g_c[(size_t)HH * BB]; // [j][row]
__device__ float g_bias[2048];

// ---- helpers ----
__device__ __forceinline__ uint32_t s2u(const void* p) {
    uint32_t a;
    asm("{ .reg .u64 t; cvta.to.shared.u64 t, %1; cvt.u32.u64 %0, t; }" : "=r"(a) : "l"(p));
    return a;
}
__device__ __forceinline__ void ldsm4(uint32_t (&r)[4], uint32_t addr) {
    asm volatile("ldmatrix.sync.aligned.m8n8.x4.shared.b16 {%0,%1,%2,%3}, [%4];"
        : "=r"(r[0]), "=r"(r[1]), "=r"(r[2]), "=r"(r[3]) : "r"(addr));
}
__device__ __forceinline__ void mma16816(float (&d)[4], const uint32_t (&a)[4],
                                         uint32_t b0, uint32_t b1) {
    asm volatile("mma.sync.aligned.m16n8k16.row.col.f32.f16.f16.f32 "
        "{%0,%1,%2,%3}, {%4,%5,%6,%7}, {%8,%9}, {%0,%1,%2,%3};"
        : "+f"(d[0]), "+f"(d[1]), "+f"(d[2]), "+f"(d[3])
        : "r"(a[0]), "r"(a[1]), "r"(a[2]), "r"(a[3]), "r"(b0), "r"(b1));
}
__device__ __forceinline__ void cpasync16(uint32_t dst, const void* src) {
    size_t g = __cvta_generic_to_global(src);
    asm volatile("cp.async.cg.shared.global [%0], [%1], 16;" :: "r"(dst), "l"(g));
}
__device__ __forceinline__ float fsig(float x) { return 1.0f / (1.0f + __expf(-x)); }
__device__ __forceinline__ float ftanh_(float x) {
    float e = __expf(2.0f * x);
    return 1.0f - 2.0f / (e + 1.0f);
}

// ---- prep kernels ----
__global__ void prep_w(const float* __restrict__ W_ih, const float* __restrict__ W_hh,
                       const float* __restrict__ b_ih, const float* __restrict__ b_hh) {
    int idx = blockIdx.x * blockDim.x + threadIdx.x;
    if (idx >= 2048 * KTOT) return;
    int C = idx / KTOT, k = idx - C * KTOT;
    int orig = (C & 3) * HH + (C >> 2);     // gate-major -> interleaved
    float v = 0.0f;
    if (k < HH) v = W_hh[(size_t)orig * HH + k];
    else if (k - HH < VV) v = W_ih[(size_t)orig * VV + (k - HH)];
    __half hi = __float2half(v);
    g_W_hi[C][k] = hi;
    g_W_lo[C][k] = __float2half(v - __half2float(hi));
    if (k == 0) g_bias[C] = b_ih[orig] + b_hh[orig];
}
__global__ void prep_x(const float* __restrict__ msgs) {
    int idx = blockIdx.x * blockDim.x + threadIdx.x;
    if (idx >= TT * BB * 32) return;
    int kk = idx & 31, rt = idx >> 5;
    int row = rt & (BB - 1), t = rt >> 11;
    float v = (kk < VV) ? msgs[((size_t)row * TT + t) * VV + kk] : 0.0f;
    __half hi = __float2half(v);
    g_x_hi[t][row][kk] = hi;
    g_x_lo[t][row][kk] = __float2half(v - __half2float(hi));
}
__global__ void init_state() {
    size_t i = (size_t)blockIdx.x * blockDim.x + threadIdx.x;
    if (i < (size_t)BB * HH) {
        g_h_hi[0][0][i] = __float2half(0.0f);
        g_h_lo[0][0][i] = __float2half(0.0f);
        g_c[i] = 0.0f;
    }
}

// ---- per-chunk producer: 4 tiles x 128 rows x 4x16B chunks / 256 thr ----
__device__ __forceinline__ void produce(uint32_t sb, int stage, int kc, int t,
                                        int row0, int C0, int tid) {
    const int hb = t & 1;
    #pragma unroll
    for (int i = 0; i < 8; i++) {
        int p = tid + i * 256;
        int tile = p >> 9;            // 0..3
        int r = (p >> 2) & 127;
        int cc = p & 3;
        int koff = kc * 32 + cc * 8;  // halves
        uint32_t dst = sb + stage * STAGE_BYTES + tile * TILE_BYTES + r * ROWB + cc * 16;
        const void* src;
        if (tile == 0)
            src = (kc < 16) ? (const void*)&g_h_hi[hb][row0 + r][koff]
                            : (const void*)&g_x_hi[t][row0 + r][koff - 512];
        else if (tile == 1)
            src = (kc < 16) ? (const void*)&g_h_lo[hb][row0 + r][koff]
                            : (const void*)&g_x_lo[t][row0 + r][koff - 512];
        else if (tile == 2)
            src = (const void*)&g_W_hi[C0 + r][koff];
        else
            src = (const void*)&g_W_lo[C0 + r][koff];
        cpasync16(dst, src);
    }
}

// ---- LSTM step: fp16-split HMMA GEMM + fused gate epilogue ----
__global__ __launch_bounds__(256, 2) void lstm_step(int t) {
    extern __shared__ __align__(1024) char smem[];
    const uint32_t sb = s2u(smem);
    const int tid = threadIdx.x;
    const int wid = tid >> 5, lane = tid & 31;
    const int wm = wid & 1;       // 2 m-blocks of 64
    const int wn = wid >> 1;      // 4 n-blocks of 32
    const int row0 = blockIdx.x * TM;
    const int C0 = blockIdx.y * TN;
    const int buf = (t + 1) & 1;

    float d[4][4][4];
    #pragma unroll
    for (int a = 0; a < 4; a++)
        #pragma unroll
        for (int b = 0; b < 4; b++)
            #pragma unroll
            for (int c = 0; c < 4; c++) d[a][b][c] = 0.0f;

    produce(sb, 0, 0, t, row0, C0, tid);
    asm volatile("cp.async.commit_group;");

    for (int kc = 0; kc < NCH; kc++) {
        if (kc + 1 < NCH) {
            produce(sb, (kc + 1) & 1, kc + 1, t, row0, C0, tid);
            asm volatile("cp.async.commit_group;");
            asm volatile("cp.async.wait_group 1;");
        } else {
            asm volatile("cp.async.wait_group 0;");
        }
        __syncthreads();

        const uint32_t st = sb + (kc & 1) * STAGE_BYTES;
        #pragma unroll
        for (int k16 = 0; k16 < 2; k16++) {
            // B fragments (NON-trans ldmatrix on [n][k] storage):
            // x4 covers 16 n-rows x 16 k: m0 = n0-7/k0-7, m1 = n0-7/k8-15,
            //                             m2 = n8-15/k0-7, m3 = n8-15/k8-15
            uint32_t bh[4][2], bl[4][2];
            #pragma unroll
            for (int g16 = 0; g16 < 2; g16++) {
                uint32_t brow = wn * 32 + g16 * 16 + ((lane >> 4) & 1) * 8 + (lane & 7);
                uint32_t ba = st + 2 * TILE_BYTES + brow * ROWB + k16 * 32
                            + ((lane >> 3) & 1) * 16;
                uint32_t r4[4];
                ldsm4(r4, ba);
                bh[g16 * 2 + 0][0] = r4[0]; bh[g16 * 2 + 0][1] = r4[1];
                bh[g16 * 2 + 1][0] = r4[2]; bh[g16 * 2 + 1][1] = r4[3];
                ldsm4(r4, ba + TILE_BYTES);
                bl[g16 * 2 + 0][0] = r4[0]; bl[g16 * 2 + 0][1] = r4[1];
                bl[g16 * 2 + 1][0] = r4[2]; bl[g16 * 2 + 1][1] = r4[3];
            }
            #pragma unroll
            for (int mf = 0; mf < 4; mf++) {
                uint32_t arow = wm * 64 + mf * 16 + (lane & 15);
                uint32_t aa = st + arow * ROWB + k16 * 32 + (lane >> 4) * 16;
                uint32_t ah[4], al[4];
                ldsm4(ah, aa);
                ldsm4(al, aa + TILE_BYTES);
                #pragma unroll
                for (int nf = 0; nf < 4; nf++) {
                    mma16816(d[mf][nf], ah, bh[nf][0], bh[nf][1]);
                    mma16816(d[mf][nf], ah, bl[nf][0], bl[nf][1]);
                    mma16816(d[mf][nf], al, bh[nf][0], bh[nf][1]);
                }
            }
        }
        __syncthreads();
    }

    // ---- fused LSTM epilogue ----
    // D frag: c0=[g][2tig], c1=[g][2tig+1], c2=[g+8][2tig], c3=[g+8][2tig+1]
    // cols are gate-interleaved (C=4j+gate): tig even holds (i,f), odd holds (g,o)
    // of unit j = nf*2 + (tig>>1); shfl_xor(1) exchanges the complementary pair.
    const int g = lane >> 2, tig = lane & 3;
    #pragma unroll
    for (int nf = 0; nf < 4; nf++) {
        int j = (C0 >> 2) + wn * 8 + nf * 2 + (tig >> 1);
        float bi = g_bias[4 * j + 0], bf = g_bias[4 * j + 1];
        float bg = g_bias[4 * j + 2], bo = g_bias[4 * j + 3];
        #pragma unroll
        for (int mf = 0; mf < 4; mf++) {
            float c0 = d[mf][nf][0], c1 = d[mf][nf][1];
            float c2 = d[mf][nf][2], c3 = d[mf][nf][3];
            float s0 = __shfl_xor_sync(0xFFFFFFFFu, c0, 1);
            float s1 = __shfl_xor_sync(0xFFFFFFFFu, c1, 1);
            float s2 = __shfl_xor_sync(0xFFFFFFFFu, c2, 1);
            float s3 = __shfl_xor_sync(0xFFFFFFFFu, c3, 1);
            int row;
            float gi, gf, gg, go;
            if (!(tig & 1)) {
                row = row0 + wm * 64 + mf * 16 + g;
                gi = c0; gf = c1; gg = s0; go = s1;
            } else {
                row = row0 + wm * 64 + mf * 16 + g + 8;
                gi = s2; gf = s3; gg = c2; go = c3;
            }
            gi = fsig(gi + bi); gf = fsig(gf + bf);
            gg = ftanh_(gg + bg); go = fsig(go + bo);
            size_t ci = (size_t)j * BB + row;
            float cn = gf * g_c[ci] + gi * gg;
            g_c[ci] = cn;
            float h = go * ftanh_(cn);
            __half hh = __float2half(h);
            g_h_hi[buf][row][j] = hh;
            g_h_lo[buf][row][j] = __float2half(h - __half2float(hh));
        }
    }
}

// ---- final FC ----
__global__ void fc_kernel(const float* __restrict__ W_fc,
                          const float* __restrict__ b_fc,
                          float* __restrict__ out)
{
    __shared__ float hs[HH];
    int b = blockIdx.x;
    for (int k = threadIdx.x; k < HH; k += blockDim.x)
        hs[k] = __half2float(g_h_hi[0][b][k]) + __half2float(g_h_lo[0][b][k]);
    __syncthreads();
    int cls = threadIdx.x;
    if (cls < NC) {
        const float* w = &W_fc[(size_t)cls * HH];
        float acc = 0.0f;
        #pragma unroll 8
        for (int k = 0; k < HH; k++) acc += hs[k] * w[k];
        out[(size_t)b * NC + cls] = acc + b_fc[cls];
    }
}

extern "C" void kernel_launch(void* const* d_in, const int* in_sizes, int n_in,
                              void* d_out, int out_size)
{
    const float* msgs = (const float*)d_in[0];
    const float* W_ih = (const float*)d_in[1];
    const float* W_hh = (const float*)d_in[2];
    const float* b_ih = (const float*)d_in[3];
    const float* b_hh = (const float*)d_in[4];
    const float* W_fc = (const float*)d_in[5];
    const float* b_fc = (const float*)d_in[6];
    float* out = (float*)d_out;

    cudaFuncSetAttribute(lstm_step, cudaFuncAttributeMaxDynamicSharedMemorySize, SMEM_TOTAL);

    prep_w<<<(2048 * KTOT + 255) / 256, 256>>>(W_ih, W_hh, b_ih, b_hh);
    prep_x<<<(TT * BB * 32 + 255) / 256, 256>>>(msgs);
    init_state<<<(BB * HH + 255) / 256, 256>>>();

    dim3 grid(BB / TM, 2048 / TN);   // 16 x 16
    for (int t = 0; t < TT; t++)
        lstm_step<<<grid, 256, SMEM_TOTAL>>>(t);

    fc_kernel<<<BB, 128>>>(W_fc, b_fc, out);
}

// round 8
// speedup vs baseline: 2.1600x; 1.0296x over previous
#include <cuda_runtime.h>
#include <cuda_fp16.h>
#include <math.h>
#include <stdint.h>

// ---- dims ----
#define BB 2048
#define TT 128
#define VV 25
#define HH 512
#define NC 100
#define KTOT 544          // 512 (h) + 32 (x padded from 25)
#define TM 128
#define TN 128
#define KCH 32            // K per chunk
#define NCH 17            // 544/32

// smem: rows of 32 halves padded to 80B (conflict-free ldmatrix)
#define ROWB 80
#define TILE_BYTES (128 * ROWB)         // 10240
#define STAGE_BYTES (4 * TILE_BYTES)    // Ahi, Alo, Bhi, Blo = 40960
#define SMEM_TOTAL (2 * STAGE_BYTES)    // 81920

// ---- persistent device state ----
__device__ __align__(1024) __half g_W_hi[2048][KTOT];   // permuted: row C=4j+gate, cols k
__device__ __align__(1024) __half g_W_lo[2048][KTOT];
__device__ __align__(1024) __half g_x_hi[TT][BB][32];
__device__ __align__(1024) __half g_x_lo[TT][BB][32];
__device__ __align__(1024) __half g_h_hi[2][BB][HH];
__device__ __align__(1024) __half g_h_lo[2][BB][HH];
__device__ __align__(1024) float  g_c[(size_t)HH * BB]; // [j][row]
__device__ float g_bias[2048];

// ---- helpers ----
__device__ __forceinline__ uint32_t s2u(const void* p) {
    uint32_t a;
    asm("{ .reg .u64 t; cvta.to.shared.u64 t, %1; cvt.u32.u64 %0, t; }" : "=r"(a) : "l"(p));
    return a;
}
__device__ __forceinline__ void ldsm4(uint32_t (&r)[4], uint32_t addr) {
    asm volatile("ldmatrix.sync.aligned.m8n8.x4.shared.b16 {%0,%1,%2,%3}, [%4];"
        : "=r"(r[0]), "=r"(r[1]), "=r"(r[2]), "=r"(r[3]) : "r"(addr));
}
__device__ __forceinline__ void mma16816(float (&d)[4], const uint32_t (&a)[4],
                                         uint32_t b0, uint32_t b1) {
    asm volatile("mma.sync.aligned.m16n8k16.row.col.f32.f16.f16.f32 "
        "{%0,%1,%2,%3}, {%4,%5,%6,%7}, {%8,%9}, {%0,%1,%2,%3};"
        : "+f"(d[0]), "+f"(d[1]), "+f"(d[2]), "+f"(d[3])
        : "r"(a[0]), "r"(a[1]), "r"(a[2]), "r"(a[3]), "r"(b0), "r"(b1));
}
__device__ __forceinline__ void cpasync16(uint32_t dst, const void* src) {
    size_t g = __cvta_generic_to_global(src);
    asm volatile("cp.async.cg.shared.global [%0], [%1], 16;" :: "r"(dst), "l"(g));
}
__device__ __forceinline__ float fsig(float x) { return 1.0f / (1.0f + __expf(-x)); }
__device__ __forceinline__ float ftanh_(float x) {
    float e = __expf(2.0f * x);
    return 1.0f - 2.0f / (e + 1.0f);
}

// ---- prep kernels ----
__global__ void prep_w(const float* __restrict__ W_ih, const float* __restrict__ W_hh,
                       const float* __restrict__ b_ih, const float* __restrict__ b_hh) {
    int idx = blockIdx.x * blockDim.x + threadIdx.x;
    if (idx >= 2048 * KTOT) return;
    int C = idx / KTOT, k = idx - C * KTOT;
    int orig = (C & 3) * HH + (C >> 2);     // gate-major -> interleaved
    float v = 0.0f;
    if (k < HH) v = W_hh[(size_t)orig * HH + k];
    else if (k - HH < VV) v = W_ih[(size_t)orig * VV + (k - HH)];
    __half hi = __float2half(v);
    g_W_hi[C][k] = hi;
    g_W_lo[C][k] = __float2half(v - __half2float(hi));
    if (k == 0) g_bias[C] = b_ih[orig] + b_hh[orig];
}
__global__ void prep_x(const float* __restrict__ msgs) {
    int idx = blockIdx.x * blockDim.x + threadIdx.x;
    if (idx >= TT * BB * 32) return;
    int kk = idx & 31, rt = idx >> 5;
    int row = rt & (BB - 1), t = rt >> 11;
    float v = (kk < VV) ? msgs[((size_t)row * TT + t) * VV + kk] : 0.0f;
    __half hi = __float2half(v);
    g_x_hi[t][row][kk] = hi;
    g_x_lo[t][row][kk] = __float2half(v - __half2float(hi));
}
__global__ void init_state() {
    size_t i = (size_t)blockIdx.x * blockDim.x + threadIdx.x;
    if (i < (size_t)BB * HH) {
        g_h_hi[0][0][i] = __float2half(0.0f);
        g_h_lo[0][0][i] = __float2half(0.0f);
        g_c[i] = 0.0f;
    }
}

// ---- per-chunk producer: 4 tiles x 128 rows x 4x16B chunks / 256 thr ----
__device__ __forceinline__ void produce(uint32_t sb, int stage, int kc, int t,
                                        int row0, int C0, int tid) {
    const int hb = t & 1;
    #pragma unroll
    for (int i = 0; i < 8; i++) {
        int p = tid + i * 256;
        int tile = p >> 9;            // 0..3
        int r = (p >> 2) & 127;
        int cc = p & 3;
        int koff = kc * 32 + cc * 8;  // halves
        uint32_t dst = sb + stage * STAGE_BYTES + tile * TILE_BYTES + r * ROWB + cc * 16;
        const void* src;
        if (tile == 0)
            src = (kc < 16) ? (const void*)&g_h_hi[hb][row0 + r][koff]
                            : (const void*)&g_x_hi[t][row0 + r][koff - 512];
        else if (tile == 1)
            src = (kc < 16) ? (const void*)&g_h_lo[hb][row0 + r][koff]
                            : (const void*)&g_x_lo[t][row0 + r][koff - 512];
        else if (tile == 2)
            src = (const void*)&g_W_hi[C0 + r][koff];
        else
            src = (const void*)&g_W_lo[C0 + r][koff];
        cpasync16(dst, src);
    }
}

// ---- LSTM step: fp16-split HMMA GEMM + fused gate epilogue ----
__global__ __launch_bounds__(256, 2) void lstm_step(int t) {
    extern __shared__ __align__(1024) char smem[];
    const uint32_t sb = s2u(smem);
    const int tid = threadIdx.x;
    const int wid = tid >> 5, lane = tid & 31;
    const int wm = wid & 1;       // 2 m-blocks of 64
    const int wn = wid >> 1;      // 4 n-blocks of 32
    const int row0 = blockIdx.x * TM;
    const int C0 = blockIdx.y * TN;
    const int buf = (t + 1) & 1;

    float d[4][4][4];
    #pragma unroll
    for (int a = 0; a < 4; a++)
        #pragma unroll
        for (int b = 0; b < 4; b++)
            #pragma unroll
            for (int c = 0; c < 4; c++) d[a][b][c] = 0.0f;

    produce(sb, 0, 0, t, row0, C0, tid);
    asm volatile("cp.async.commit_group;");

    for (int kc = 0; kc < NCH; kc++) {
        if (kc + 1 < NCH) {
            produce(sb, (kc + 1) & 1, kc + 1, t, row0, C0, tid);
            asm volatile("cp.async.commit_group;");
            asm volatile("cp.async.wait_group 1;");
        } else {
            asm volatile("cp.async.wait_group 0;");
        }
        __syncthreads();

        const uint32_t st = sb + (kc & 1) * STAGE_BYTES;
        #pragma unroll
        for (int k16 = 0; k16 < 2; k16++) {
            // B fragments (NON-trans ldmatrix on [n][k] storage):
            // x4 covers 16 n-rows x 16 k: m0 = n0-7/k0-7, m1 = n0-7/k8-15,
            //                             m2 = n8-15/k0-7, m3 = n8-15/k8-15
            uint32_t bh[4][2], bl[4][2];
            #pragma unroll
            for (int g16 = 0; g16 < 2; g16++) {
                uint32_t brow = wn * 32 + g16 * 16 + ((lane >> 4) & 1) * 8 + (lane & 7);
                uint32_t ba = st + 2 * TILE_BYTES + brow * ROWB + k16 * 32
                            + ((lane >> 3) & 1) * 16;
                uint32_t r4[4];
                ldsm4(r4, ba);
                bh[g16 * 2 + 0][0] = r4[0]; bh[g16 * 2 + 0][1] = r4[1];
                bh[g16 * 2 + 1][0] = r4[2]; bh[g16 * 2 + 1][1] = r4[3];
                ldsm4(r4, ba + TILE_BYTES);
                bl[g16 * 2 + 0][0] = r4[0]; bl[g16 * 2 + 0][1] = r4[1];
                bl[g16 * 2 + 1][0] = r4[2]; bl[g16 * 2 + 1][1] = r4[3];
            }
            // mf-pair interleaved, term-major MMA issue:
            // same-accumulator reuse distance = 8 MMAs (RAW chain fully hidden)
            #pragma unroll
            for (int mp = 0; mp < 2; mp++) {
                uint32_t ah[2][4], al[2][4];
                #pragma unroll
                for (int mi = 0; mi < 2; mi++) {
                    uint32_t arow = wm * 64 + (mp * 2 + mi) * 16 + (lane & 15);
                    uint32_t aa = st + arow * ROWB + k16 * 32 + (lane >> 4) * 16;
                    ldsm4(ah[mi], aa);
                    ldsm4(al[mi], aa + TILE_BYTES);
                }
                #pragma unroll
                for (int mi = 0; mi < 2; mi++)
                    #pragma unroll
                    for (int nf = 0; nf < 4; nf++)
                        mma16816(d[mp * 2 + mi][nf], ah[mi], bh[nf][0], bh[nf][1]);
                #pragma unroll
                for (int mi = 0; mi < 2; mi++)
                    #pragma unroll
                    for (int nf = 0; nf < 4; nf++)
                        mma16816(d[mp * 2 + mi][nf], ah[mi], bl[nf][0], bl[nf][1]);
                #pragma unroll
                for (int mi = 0; mi < 2; mi++)
                    #pragma unroll
                    for (int nf = 0; nf < 4; nf++)
                        mma16816(d[mp * 2 + mi][nf], al[mi], bh[nf][0], bh[nf][1]);
            }
        }
        __syncthreads();
    }

    // ---- fused LSTM epilogue ----
    // D frag: c0=[g][2tig], c1=[g][2tig+1], c2=[g+8][2tig], c3=[g+8][2tig+1]
    // cols are gate-interleaved (C=4j+gate): tig even holds (i,f), odd holds (g,o)
    // of unit j = nf*2 + (tig>>1); shfl_xor(1) exchanges the complementary pair.
    const int g = lane >> 2, tig = lane & 3;
    #pragma unroll
    for (int nf = 0; nf < 4; nf++) {
        int j = (C0 >> 2) + wn * 8 + nf * 2 + (tig >> 1);
        float bi = g_bias[4 * j + 0], bf = g_bias[4 * j + 1];
        float bg = g_bias[4 * j + 2], bo = g_bias[4 * j + 3];
        #pragma unroll
        for (int mf = 0; mf < 4; mf++) {
            float c0 = d[mf][nf][0], c1 = d[mf][nf][1];
            float c2 = d[mf][nf][2], c3 = d[mf][nf][3];
            float s0 = __shfl_xor_sync(0xFFFFFFFFu, c0, 1);
            float s1 = __shfl_xor_sync(0xFFFFFFFFu, c1, 1);
            float s2 = __shfl_xor_sync(0xFFFFFFFFu, c2, 1);
            float s3 = __shfl_xor_sync(0xFFFFFFFFu, c3, 1);
            int row;
            float gi, gf, gg, go;
            if (!(tig & 1)) {
                row = row0 + wm * 64 + mf * 16 + g;
                gi = c0; gf = c1; gg = s0; go = s1;
            } else {
                row = row0 + wm * 64 + mf * 16 + g + 8;
                gi = s2; gf = s3; gg = c2; go = c3;
            }
            gi = fsig(gi + bi); gf = fsig(gf + bf);
            gg = ftanh_(gg + bg); go = fsig(go + bo);
            size_t ci = (size_t)j * BB + row;
            float cn = gf * g_c[ci] + gi * gg;
            g_c[ci] = cn;
            float h = go * ftanh_(cn);
            __half hh = __float2half(h);
            g_h_hi[buf][row][j] = hh;
            g_h_lo[buf][row][j] = __float2half(h - __half2float(hh));
        }
    }
}

// ---- final FC ----
__global__ void fc_kernel(const float* __restrict__ W_fc,
                          const float* __restrict__ b_fc,
                          float* __restrict__ out)
{
    __shared__ float hs[HH];
    int b = blockIdx.x;
    for (int k = threadIdx.x; k < HH; k += blockDim.x)
        hs[k] = __half2float(g_h_hi[0][b][k]) + __half2float(g_h_lo[0][b][k]);
    __syncthreads();
    int cls = threadIdx.x;
    if (cls < NC) {
        const float* w = &W_fc[(size_t)cls * HH];
        float acc = 0.0f;
        #pragma unroll 8
        for (int k = 0; k < HH; k++) acc += hs[k] * w[k];
        out[(size_t)b * NC + cls] = acc + b_fc[cls];
    }
}

extern "C" void kernel_launch(void* const* d_in, const int* in_sizes, int n_in,
                              void* d_out, int out_size)
{
    const float* msgs = (const float*)d_in[0];
    const float* W_ih = (const float*)d_in[1];
    const float* W_hh = (const float*)d_in[2];
    const float* b_ih = (const float*)d_in[3];
    const float* b_hh = (const float*)d_in[4];
    const float* W_fc = (const float*)d_in[5];
    const float* b_fc = (const float*)d_in[6];
    float* out = (float*)d_out;

    cudaFuncSetAttribute(lstm_step, cudaFuncAttributeMaxDynamicSharedMemorySize, SMEM_TOTAL);

    prep_w<<<(2048 * KTOT + 255) / 256, 256>>>(W_ih, W_hh, b_ih, b_hh);
    prep_x<<<(TT * BB * 32 + 255) / 256, 256>>>(msgs);
    init_state<<<(BB * HH + 255) / 256, 256>>>();

    dim3 grid(BB / TM, 2048 / TN);   // 16 x 16
    for (int t = 0; t < TT; t++)
        lstm_step<<<grid, 256, SMEM_TOTAL>>>(t);

    fc_kernel<<<BB, 128>>>(W_fc, b_fc, out);
}

// round 9
// speedup vs baseline: 2.1933x; 1.0154x over previous
#include <cuda_runtime.h>
#include <cuda_fp16.h>
#include <math.h>
#include <stdint.h>

// ---- dims ----
#define BB 2048
#define TT 128
#define VV 25
#define HH 512
#define NC 100
#define KTOT 544          // 512 (h) + 32 (x padded from 25)
#define TM 128
#define TN 128
#define KCH 32            // K per chunk
#define NCH 17            // 544/32

// smem: rows of 32 halves padded to 80B (conflict-free ldmatrix)
#define ROWB 80
#define TILE_BYTES (128 * ROWB)         // 10240
#define STAGE_BYTES (4 * TILE_BYTES)    // Ahi, Alo, Bhi, Blo = 40960
#define SMEM_TOTAL (2 * STAGE_BYTES)    // 81920

// ---- persistent device state ----
__device__ __align__(1024) __half g_W_hi[2048][KTOT];   // permuted: row C=4j+gate, cols k
__device__ __align__(1024) __half g_W_lo[2048][KTOT];
__device__ __align__(1024) __half g_x_hi[TT][BB][32];
__device__ __align__(1024) __half g_x_lo[TT][BB][32];
__device__ __align__(1024) __half g_h_hi[2][BB][HH];
__device__ __align__(1024) __half g_h_lo[2][BB][HH];
__device__ __align__(1024) float  g_c[(size_t)HH * BB]; // [j][row]
__device__ float g_bias[2048];

// ---- helpers ----
__device__ __forceinline__ uint32_t s2u(const void* p) {
    uint32_t a;
    asm("{ .reg .u64 t; cvta.to.shared.u64 t, %1; cvt.u32.u64 %0, t; }" : "=r"(a) : "l"(p));
    return a;
}
__device__ __forceinline__ void ldsm4(uint32_t (&r)[4], uint32_t addr) {
    asm volatile("ldmatrix.sync.aligned.m8n8.x4.shared.b16 {%0,%1,%2,%3}, [%4];"
        : "=r"(r[0]), "=r"(r[1]), "=r"(r[2]), "=r"(r[3]) : "r"(addr));
}
__device__ __forceinline__ void mma16816(float (&d)[4], const uint32_t (&a)[4],
                                         uint32_t b0, uint32_t b1) {
    asm volatile("mma.sync.aligned.m16n8k16.row.col.f32.f16.f16.f32 "
        "{%0,%1,%2,%3}, {%4,%5,%6,%7}, {%8,%9}, {%0,%1,%2,%3};"
        : "+f"(d[0]), "+f"(d[1]), "+f"(d[2]), "+f"(d[3])
        : "r"(a[0]), "r"(a[1]), "r"(a[2]), "r"(a[3]), "r"(b0), "r"(b1));
}
__device__ __forceinline__ void cpasync16(uint32_t dst, const void* src) {
    size_t g = __cvta_generic_to_global(src);
    asm volatile("cp.async.cg.shared.global [%0], [%1], 16;" :: "r"(dst), "l"(g));
}
__device__ __forceinline__ float fsig(float x) { return 1.0f / (1.0f + __expf(-x)); }
__device__ __forceinline__ float ftanh_(float x) {
    float e = __expf(2.0f * x);
    return 1.0f - 2.0f / (e + 1.0f);
}

// ---- prep kernels ----
__global__ void prep_w(const float* __restrict__ W_ih, const float* __restrict__ W_hh,
                       const float* __restrict__ b_ih, const float* __restrict__ b_hh) {
    int idx = blockIdx.x * blockDim.x + threadIdx.x;
    if (idx >= 2048 * KTOT) return;
    int C = idx / KTOT, k = idx - C * KTOT;
    int orig = (C & 3) * HH + (C >> 2);     // gate-major -> interleaved
    float v = 0.0f;
    if (k < HH) v = W_hh[(size_t)orig * HH + k];
    else if (k - HH < VV) v = W_ih[(size_t)orig * VV + (k - HH)];
    __half hi = __float2half(v);
    g_W_hi[C][k] = hi;
    g_W_lo[C][k] = __float2half(v - __half2float(hi));
    if (k == 0) g_bias[C] = b_ih[orig] + b_hh[orig];
}
__global__ void prep_x(const float* __restrict__ msgs) {
    int idx = blockIdx.x * blockDim.x + threadIdx.x;
    if (idx >= TT * BB * 32) return;
    int kk = idx & 31, rt = idx >> 5;
    int row = rt & (BB - 1), t = rt >> 11;
    float v = (kk < VV) ? msgs[((size_t)row * TT + t) * VV + kk] : 0.0f;
    __half hi = __float2half(v);
    g_x_hi[t][row][kk] = hi;
    g_x_lo[t][row][kk] = __float2half(v - __half2float(hi));
}
__global__ void init_state() {
    size_t i = (size_t)blockIdx.x * blockDim.x + threadIdx.x;
    if (i < (size_t)BB * HH) {
        g_h_hi[0][0][i] = __float2half(0.0f);
        g_h_lo[0][0][i] = __float2half(0.0f);
        g_c[i] = 0.0f;
    }
}

// ---- per-chunk producer: 4 tiles x 128 rows x 4x16B chunks / 256 thr ----
__device__ __forceinline__ void produce(uint32_t sb, int stage, int kc, int t,
                                        int row0, int C0, int tid) {
    const int hb = t & 1;
    #pragma unroll
    for (int i = 0; i < 8; i++) {
        int p = tid + i * 256;
        int tile = p >> 9;            // 0..3
        int r = (p >> 2) & 127;
        int cc = p & 3;
        int koff = kc * 32 + cc * 8;  // halves
        uint32_t dst = sb + stage * STAGE_BYTES + tile * TILE_BYTES + r * ROWB + cc * 16;
        const void* src;
        if (tile == 0)
            src = (kc < 16) ? (const void*)&g_h_hi[hb][row0 + r][koff]
                            : (const void*)&g_x_hi[t][row0 + r][koff - 512];
        else if (tile == 1)
            src = (kc < 16) ? (const void*)&g_h_lo[hb][row0 + r][koff]
                            : (const void*)&g_x_lo[t][row0 + r][koff - 512];
        else if (tile == 2)
            src = (const void*)&g_W_hi[C0 + r][koff];
        else
            src = (const void*)&g_W_lo[C0 + r][koff];
        cpasync16(dst, src);
    }
}

// ---- LSTM step: fp16-split HMMA GEMM + fused gate epilogue ----
__global__ __launch_bounds__(256, 2) void lstm_step(int t) {
    extern __shared__ __align__(1024) char smem[];
    const uint32_t sb = s2u(smem);
    const int tid = threadIdx.x;
    const int wid = tid >> 5, lane = tid & 31;
    const int wm = wid & 1;       // 2 m-blocks of 64
    const int wn = wid >> 1;      // 4 n-blocks of 32
    const int row0 = blockIdx.x * TM;
    const int C0 = blockIdx.y * TN;
    const int buf = (t + 1) & 1;

    float d[4][4][4];
    #pragma unroll
    for (int a = 0; a < 4; a++)
        #pragma unroll
        for (int b = 0; b < 4; b++)
            #pragma unroll
            for (int c = 0; c < 4; c++) d[a][b][c] = 0.0f;

    produce(sb, 0, 0, t, row0, C0, tid);
    asm volatile("cp.async.commit_group;");

    // per-warp invariant pieces of the ldmatrix addresses
    const uint32_t b_lane = (wn * 32 + ((lane >> 4) & 1) * 8 + (lane & 7)) * ROWB
                          + ((lane >> 3) & 1) * 16 + 2 * TILE_BYTES;
    const uint32_t a_lane = (wm * 64 + (lane & 15)) * ROWB + (lane >> 4) * 16;

    for (int kc = 0; kc < NCH; kc++) {
        // all previously committed groups (i.e. chunk kc) must have landed
        asm volatile("cp.async.wait_group 0;");
        __syncthreads();
        // issue next chunk AFTER the barrier: every thread is done reading
        // the stage this write targets (stage (kc+1)&1, last read at kc-1)
        if (kc + 1 < NCH) {
            produce(sb, (kc + 1) & 1, kc + 1, t, row0, C0, tid);
            asm volatile("cp.async.commit_group;");
        }

        const uint32_t st = sb + (kc & 1) * STAGE_BYTES;
        #pragma unroll
        for (int k16 = 0; k16 < 2; k16++) {
            const uint32_t kb = k16 * 32;
            // ---- hoist ALL fragment loads (12 ldsm) before any MMA ----
            uint32_t bh[4][2], bl[4][2];
            #pragma unroll
            for (int g16 = 0; g16 < 2; g16++) {
                uint32_t ba = st + b_lane + g16 * (16 * ROWB) + kb;
                uint32_t r4[4];
                ldsm4(r4, ba);
                bh[g16 * 2 + 0][0] = r4[0]; bh[g16 * 2 + 0][1] = r4[1];
                bh[g16 * 2 + 1][0] = r4[2]; bh[g16 * 2 + 1][1] = r4[3];
                ldsm4(r4, ba + TILE_BYTES);
                bl[g16 * 2 + 0][0] = r4[0]; bl[g16 * 2 + 0][1] = r4[1];
                bl[g16 * 2 + 1][0] = r4[2]; bl[g16 * 2 + 1][1] = r4[3];
            }
            uint32_t ah[4][4], al[4][4];
            #pragma unroll
            for (int mf = 0; mf < 4; mf++) {
                uint32_t aa = st + a_lane + mf * (16 * ROWB) + kb;
                ldsm4(ah[mf], aa);
                ldsm4(al[mf], aa + TILE_BYTES);
            }
            // ---- 48 MMAs, no smem dependency left; term-major for RAW spacing ----
            #pragma unroll
            for (int mf = 0; mf < 4; mf++)
                #pragma unroll
                for (int nf = 0; nf < 4; nf++)
                    mma16816(d[mf][nf], ah[mf], bh[nf][0], bh[nf][1]);
            #pragma unroll
            for (int mf = 0; mf < 4; mf++)
                #pragma unroll
                for (int nf = 0; nf < 4; nf++)
                    mma16816(d[mf][nf], ah[mf], bl[nf][0], bl[nf][1]);
            #pragma unroll
            for (int mf = 0; mf < 4; mf++)
                #pragma unroll
                for (int nf = 0; nf < 4; nf++)
                    mma16816(d[mf][nf], al[mf], bh[nf][0], bh[nf][1]);
        }
    }

    // ---- fused LSTM epilogue ----
    // D frag: c0=[g][2tig], c1=[g][2tig+1], c2=[g+8][2tig], c3=[g+8][2tig+1]
    // cols are gate-interleaved (C=4j+gate): tig even holds (i,f), odd holds (g,o)
    // of unit j = nf*2 + (tig>>1); shfl_xor(1) exchanges the complementary pair.
    const int g = lane >> 2, tig = lane & 3;
    #pragma unroll
    for (int nf = 0; nf < 4; nf++) {
        int j = (C0 >> 2) + wn * 8 + nf * 2 + (tig >> 1);
        float bi = g_bias[4 * j + 0], bf = g_bias[4 * j + 1];
        float bg = g_bias[4 * j + 2], bo = g_bias[4 * j + 3];
        #pragma unroll
        for (int mf = 0; mf < 4; mf++) {
            float c0 = d[mf][nf][0], c1 = d[mf][nf][1];
            float c2 = d[mf][nf][2], c3 = d[mf][nf][3];
            float s0 = __shfl_xor_sync(0xFFFFFFFFu, c0, 1);
            float s1 = __shfl_xor_sync(0xFFFFFFFFu, c1, 1);
            float s2 = __shfl_xor_sync(0xFFFFFFFFu, c2, 1);
            float s3 = __shfl_xor_sync(0xFFFFFFFFu, c3, 1);
            int row;
            float gi, gf, gg, go;
            if (!(tig & 1)) {
                row = row0 + wm * 64 + mf * 16 + g;
                gi = c0; gf = c1; gg = s0; go = s1;
            } else {
                row = row0 + wm * 64 + mf * 16 + g + 8;
                gi = s2; gf = s3; gg = c2; go = c3;
            }
            gi = fsig(gi + bi); gf = fsig(gf + bf);
            gg = ftanh_(gg + bg); go = fsig(go + bo);
            size_t ci = (size_t)j * BB + row;
            float cn = gf * g_c[ci] + gi * gg;
            g_c[ci] = cn;
            float h = go * ftanh_(cn);
            __half hh = __float2half(h);
            g_h_hi[buf][row][j] = hh;
            g_h_lo[buf][row][j] = __float2half(h - __half2float(hh));
        }
    }
}

// ---- final FC ----
__global__ void fc_kernel(const float* __restrict__ W_fc,
                          const float* __restrict__ b_fc,
                          float* __restrict__ out)
{
    __shared__ float hs[HH];
    int b = blockIdx.x;
    for (int k = threadIdx.x; k < HH; k += blockDim.x)
        hs[k] = __half2float(g_h_hi[0][b][k]) + __half2float(g_h_lo[0][b][k]);
    __syncthreads();
    int cls = threadIdx.x;
    if (cls < NC) {
        const float* w = &W_fc[(size_t)cls * HH];
        float acc = 0.0f;
        #pragma unroll 8
        for (int k = 0; k < HH; k++) acc += hs[k] * w[k];
        out[(size_t)b * NC + cls] = acc + b_fc[cls];
    }
}

extern "C" void kernel_launch(void* const* d_in, const int* in_sizes, int n_in,
                              void* d_out, int out_size)
{
    const float* msgs = (const float*)d_in[0];
    const float* W_ih = (const float*)d_in[1];
    const float* W_hh = (const float*)d_in[2];
    const float* b_ih = (const float*)d_in[3];
    const float* b_hh = (const float*)d_in[4];
    const float* W_fc = (const float*)d_in[5];
    const float* b_fc = (const float*)d_in[6];
    float* out = (float*)d_out;

    cudaFuncSetAttribute(lstm_step, cudaFuncAttributeMaxDynamicSharedMemorySize, SMEM_TOTAL);

    prep_w<<<(2048 * KTOT + 255) / 256, 256>>>(W_ih, W_hh, b_ih, b_hh);
    prep_x<<<(TT * BB * 32 + 255) / 256, 256>>>(msgs);
    init_state<<<(BB * HH + 255) / 256, 256>>>();

    dim3 grid(BB / TM, 2048 / TN);   // 16 x 16
    for (int t = 0; t < TT; t++)
        lstm_step<<<grid, 256, SMEM_TOTAL>>>(t);

    fc_kernel<<<BB, 128>>>(W_fc, b_fc, out);
}